// round 15
// baseline (speedup 1.0000x reference)
#include <cuda_runtime.h>
#include <cuda_bf16.h>
#include <cuda_fp16.h>
#include <math.h>

#define N_USERS   50000
#define N_ENT     100000
#define N_NODES   150000
#define N_EDGES   3000000
#define BATCH     8192
#define OUT_COLS  176
#define LEAKY     0.2f

// ---------------- scratch (device globals) -----------------------------------
__device__ float4 g_egoA4[N_NODES * 16];        // layer outputs (<=64 floats/row)
__device__ float4 g_egoB4[N_NODES * 16];
__device__ float4 g_x4  [N_NODES * 32];         // packed {xs,xb} pairs (max 64in)
__device__ float4 g_all4[N_NODES * 44];         // cols [64,176) used
__device__ __half2 g_ego16[N_NODES * 32];       // fp16 gather shadow
__device__ __align__(16) long long g_pairs[N_EDGES];  // {a:hi32, t:lo32} grouped by h
__device__ int g_rowptr[N_NODES + 1];
__device__ int g_cursor[N_NODES];
__device__ volatile unsigned long long g_chain[256];  // packed {flag:bit62, prefix:lo32}

#define SCAN_BLOCKS 147                          // 147*1024 >= 150000

// ---------------- f32x2 packed helpers ---------------------------------------
__device__ __forceinline__ unsigned long long pk2(float a, float b) {
    unsigned long long r;
    asm("mov.b64 %0, {%1,%2};" : "=l"(r) : "f"(a), "f"(b));
    return r;
}
__device__ __forceinline__ void upk2(unsigned long long v, float& a, float& b) {
    asm("mov.b64 {%0,%1}, %2;" : "=f"(a), "=f"(b) : "l"(v));
}
__device__ __forceinline__ void ffma2(unsigned long long& acc,
                                      unsigned long long a,
                                      unsigned long long b) {
    asm("fma.rn.f32x2 %0, %1, %2, %0;" : "+l"(acc) : "l"(a), "l"(b));
}
__device__ __forceinline__ longlong2 ldg_ll2(const long long* p) {
    return __ldg(reinterpret_cast<const longlong2*>(p));
}
// load 4 halves (dims 4l..4l+3) -> float4
__device__ __forceinline__ float4 ldg_h4(const __half2* p) {
    uint2 raw = __ldg(reinterpret_cast<const uint2*>(p));
    __half2 h0 = *reinterpret_cast<__half2*>(&raw.x);
    __half2 h1 = *reinterpret_cast<__half2*>(&raw.y);
    float2 f0 = __half22float2(h0);
    float2 f1 = __half22float2(h1);
    return make_float4(f0.x, f0.y, f1.x, f1.y);
}

// ---------------- conv0: fp16 shadow of layer-0 ego + state reset -------------
__global__ void conv0_kernel(const float2* __restrict__ u2,
                             const float2* __restrict__ e2) {
    int gid = blockIdx.x * blockDim.x + threadIdx.x;
    if (gid < N_NODES) g_cursor[gid] = 0;            // replaces memsetAsync
    if (gid < 256)     g_chain[gid] = 0ULL;          // reset scan chain (graph replays!)
    if (gid >= N_NODES * 32) return;
    float2 v = (gid < N_USERS * 32) ? u2[gid] : e2[gid - N_USERS * 32];
    g_ego16[gid] = __float22half2_rn(v);
}

// ================= CSR build ==================================================
__global__ void hist_kernel(const int* __restrict__ all_h) {
    int e = blockIdx.x * blockDim.x + threadIdx.x;
    if (e < N_EDGES) atomicAdd(&g_cursor[e < N_EDGES ? all_h[e] : 0], 1);
}

// single-kernel chained exclusive scan; flag+prefix packed in ONE 64-bit word
// (single volatile 8B load is atomic -> no flag/value ordering window).
// 147 blocks, all resident on 148 SMs -> spin is deadlock-free.
__global__ void scan_kernel() {
    __shared__ int sm[256];
    __shared__ int s_prefix;
    int tid = threadIdx.x;
    int bid = blockIdx.x;
    int base = bid * 1024 + tid * 4;
    int d[4]; int s = 0;
    #pragma unroll
    for (int k = 0; k < 4; k++) {
        int idx = base + k;
        d[k] = (idx < N_NODES) ? g_cursor[idx] : 0;
        s += d[k];
    }
    sm[tid] = s; __syncthreads();
    for (int o = 1; o < 256; o <<= 1) {               // inclusive block scan
        int t = (tid >= o) ? sm[tid - o] : 0;
        __syncthreads();
        sm[tid] += t;
        __syncthreads();
    }
    if (tid == 0) {
        int prefix = 0;
        if (bid > 0) {
            unsigned long long v;
            do { v = g_chain[bid - 1]; } while (!(v >> 62));
            prefix = (int)(v & 0xffffffffULL);
        }
        s_prefix = prefix;
        g_chain[bid] = (1ULL << 62) | (unsigned long long)(unsigned)(prefix + sm[255]);
        if (bid == SCAN_BLOCKS - 1) g_rowptr[N_NODES] = N_EDGES;
    }
    __syncthreads();
    int run = s_prefix + sm[tid] - s;                 // exclusive start
    #pragma unroll
    for (int k = 0; k < 4; k++) {
        int idx = base + k;
        if (idx < N_NODES) {
            g_rowptr[idx] = run;
            g_cursor[idx] = run;
            run += d[k];
        }
    }
}

__global__ void fill_kernel(const int* __restrict__ all_h,
                            const int* __restrict__ all_t,
                            const float* __restrict__ A) {
    int e = blockIdx.x * blockDim.x + threadIdx.x;
    if (e >= N_EDGES) return;
    int h = all_h[e];
    int p = atomicAdd(&g_cursor[h], 1);
    unsigned long long q = (unsigned long long)(unsigned)all_t[e]
                         | ((unsigned long long)__float_as_uint(A[e]) << 32);
    g_pairs[p] = (long long)q;
}

// ================= aggregation ================================================
__device__ __forceinline__ void unpack_pair(long long q, int& t, float& a) {
    t = (int)(unsigned)q;
    a = __uint_as_float((unsigned)((unsigned long long)q >> 32));
}

// DIN=64: 16 lanes/node, lane l owns dims [4l,4l+4). Gathers from fp16 shadow
// (LDG.64); self term fp32. Pairs read as longlong2.
template <bool SPLIT>
__global__ void agg64_kernel(const float4* __restrict__ egoU,
                             const float4* __restrict__ egoE,
                             float4* __restrict__ x4) {
    int ghw = (blockIdx.x * blockDim.x + threadIdx.x) >> 4;   // node id
    int l   = threadIdx.x & 15;
    if (ghw >= N_NODES) return;
    int s   = __ldg(g_rowptr + ghw);
    int end = __ldg(g_rowptr + ghw + 1);
    float ax = 0.f, ay = 0.f, az = 0.f, aw = 0.f;
    int e = s;
    if (e < end && (e & 1)) {
        int t; float a;
        unpack_pair(__ldg(g_pairs + e), t, a);
        float4 v = ldg_h4(g_ego16 + (size_t)t * 32 + 2 * l);
        ax += a * v.x; ay += a * v.y; az += a * v.z; aw += a * v.w;
        e++;
    }
    for (; e + 4 <= end; e += 4) {
        longlong2 q01 = ldg_ll2(g_pairs + e);
        longlong2 q23 = ldg_ll2(g_pairs + e + 2);
        int t0, t1, t2, t3; float a0, a1, a2, a3;
        unpack_pair(q01.x, t0, a0); unpack_pair(q01.y, t1, a1);
        unpack_pair(q23.x, t2, a2); unpack_pair(q23.y, t3, a3);
        float4 v0 = ldg_h4(g_ego16 + (size_t)t0 * 32 + 2 * l);
        float4 v1 = ldg_h4(g_ego16 + (size_t)t1 * 32 + 2 * l);
        float4 v2 = ldg_h4(g_ego16 + (size_t)t2 * 32 + 2 * l);
        float4 v3 = ldg_h4(g_ego16 + (size_t)t3 * 32 + 2 * l);
        ax += a0 * v0.x; ay += a0 * v0.y; az += a0 * v0.z; aw += a0 * v0.w;
        ax += a1 * v1.x; ay += a1 * v1.y; az += a1 * v1.z; aw += a1 * v1.w;
        ax += a2 * v2.x; ay += a2 * v2.y; az += a2 * v2.z; aw += a2 * v2.w;
        ax += a3 * v3.x; ay += a3 * v3.y; az += a3 * v3.z; aw += a3 * v3.w;
    }
    for (; e < end; e++) {
        int t; float a;
        unpack_pair(__ldg(g_pairs + e), t, a);
        float4 v = ldg_h4(g_ego16 + (size_t)t * 32 + 2 * l);
        ax += a * v.x; ay += a * v.y; az += a * v.z; aw += a * v.w;
    }
    const float4* ps = (!SPLIT || ghw < N_USERS) ? (egoU + (size_t)ghw * 16)
                                                 : (egoE + (size_t)(ghw - N_USERS) * 16);
    float4 eg = __ldg(ps + l);
    x4[(size_t)ghw * 32 + 2 * l]     = make_float4(eg.x + ax, eg.x * ax, eg.y + ay, eg.y * ay);
    x4[(size_t)ghw * 32 + 2 * l + 1] = make_float4(eg.z + az, eg.z * az, eg.w + aw, eg.w * aw);
}

// DIN=32: 8 lanes/node, lane l owns dims [4l,4l+4). fp16 gathers, fp32 self.
__global__ void agg32_kernel(const float4* __restrict__ ego4,
                             float4* __restrict__ x4out) {
    int ghw = (blockIdx.x * blockDim.x + threadIdx.x) >> 3;
    int l   = threadIdx.x & 7;
    if (ghw >= N_NODES) return;
    int s   = __ldg(g_rowptr + ghw);
    int end = __ldg(g_rowptr + ghw + 1);
    float ax = 0.f, ay = 0.f, az = 0.f, aw = 0.f;
    int e = s;
    if (e < end && (e & 1)) {
        int t; float a;
        unpack_pair(__ldg(g_pairs + e), t, a);
        float4 v = ldg_h4(g_ego16 + (size_t)t * 16 + 2 * l);
        ax += a * v.x; ay += a * v.y; az += a * v.z; aw += a * v.w;
        e++;
    }
    for (; e + 4 <= end; e += 4) {
        longlong2 q01 = ldg_ll2(g_pairs + e);
        longlong2 q23 = ldg_ll2(g_pairs + e + 2);
        int t0, t1, t2, t3; float a0, a1, a2, a3;
        unpack_pair(q01.x, t0, a0); unpack_pair(q01.y, t1, a1);
        unpack_pair(q23.x, t2, a2); unpack_pair(q23.y, t3, a3);
        float4 v0 = ldg_h4(g_ego16 + (size_t)t0 * 16 + 2 * l);
        float4 v1 = ldg_h4(g_ego16 + (size_t)t1 * 16 + 2 * l);
        float4 v2 = ldg_h4(g_ego16 + (size_t)t2 * 16 + 2 * l);
        float4 v3 = ldg_h4(g_ego16 + (size_t)t3 * 16 + 2 * l);
        ax += a0 * v0.x; ay += a0 * v0.y; az += a0 * v0.z; aw += a0 * v0.w;
        ax += a1 * v1.x; ay += a1 * v1.y; az += a1 * v1.z; aw += a1 * v1.w;
        ax += a2 * v2.x; ay += a2 * v2.y; az += a2 * v2.z; aw += a2 * v2.w;
        ax += a3 * v3.x; ay += a3 * v3.y; az += a3 * v3.z; aw += a3 * v3.w;
    }
    for (; e < end; e++) {
        int t; float a;
        unpack_pair(__ldg(g_pairs + e), t, a);
        float4 v = ldg_h4(g_ego16 + (size_t)t * 16 + 2 * l);
        ax += a * v.x; ay += a * v.y; az += a * v.z; aw += a * v.w;
    }
    float4 eg = __ldg(ego4 + (size_t)ghw * 8 + l);
    x4out[(size_t)ghw * 16 + 2 * l]     = make_float4(eg.x + ax, eg.x * ax, eg.y + ay, eg.y * ay);
    x4out[(size_t)ghw * 16 + 2 * l + 1] = make_float4(eg.z + az, eg.z * az, eg.w + aw, eg.w * aw);
}

// ================= GEMM + leaky + norm (2-col threads, packed f32x2) ==========
// WEGO: write fp32 ego_out; W16: write fp16 shadow for next layer's gathers.
template <int DIN, int DOUT, int R, bool WEGO, bool W16>
__global__ void __launch_bounds__(256)
gemm_kernel(const float4* __restrict__ x4,
            float* __restrict__ ego_out,
            const float* __restrict__ Wg,
            const float* __restrict__ bg,
            const float* __restrict__ Wb,
            const float* __restrict__ bb,
            float* __restrict__ all_emb,
            int col_off) {
    constexpr int I2   = DIN / 2;
    constexpr int JW   = DOUT / 2;      // threads per row-group
    constexpr int JG   = 256 / JW;      // row-groups per block
    constexpr int ROWS = JG * R;

    extern __shared__ float4 dyn4[];
    float4* sWa   = dyn4;                       // [JW][I2+1]
    float4* sWb   = sWa + JW * (I2 + 1);        // [JW][I2+1]
    float4* sx    = sWb + JW * (I2 + 1);        // [ROWS][I2]
    float4* sbias = sx + ROWS * I2;             // [JW]

    int tid = threadIdx.x;
    for (int k = tid; k < JW * I2; k += 256) {
        int j  = k % JW;
        int i2 = k / JW;
        sWa[j * (I2 + 1) + i2] = make_float4(Wg[(2 * i2)     * DOUT + j],
                                             Wb[(2 * i2)     * DOUT + j],
                                             Wg[(2 * i2 + 1) * DOUT + j],
                                             Wb[(2 * i2 + 1) * DOUT + j]);
        int j2 = j + JW;
        sWb[j * (I2 + 1) + i2] = make_float4(Wg[(2 * i2)     * DOUT + j2],
                                             Wb[(2 * i2)     * DOUT + j2],
                                             Wg[(2 * i2 + 1) * DOUT + j2],
                                             Wb[(2 * i2 + 1) * DOUT + j2]);
    }
    if (tid < JW) sbias[tid] = make_float4(bg[tid], bb[tid], bg[tid + JW], bb[tid + JW]);
    __syncthreads();

    int rg = tid / JW;
    int j  = tid % JW;
    float4 bia = sbias[j];
    __half* e16 = reinterpret_cast<__half*>(g_ego16);

    for (int base = blockIdx.x * ROWS; base < N_NODES; base += gridDim.x * ROWS) {
        {
            const float4* src = x4 + (size_t)base * I2;
            int limit = (N_NODES - base) * I2;
            int total = ROWS * I2;
            for (int k = tid; k < total; k += 256)
                if (k < limit) sx[k] = src[k];
        }
        __syncthreads();

        unsigned long long acca[R], accb[R];
        #pragma unroll
        for (int rr = 0; rr < R; rr++) {
            acca[rr] = pk2(bia.x, bia.y);
            accb[rr] = pk2(bia.z, bia.w);
        }

        #pragma unroll
        for (int i2 = 0; i2 < I2; i2++) {
            float4 wa = sWa[j * (I2 + 1) + i2];
            float4 wb = sWb[j * (I2 + 1) + i2];
            unsigned long long wa01 = pk2(wa.x, wa.y), wa23 = pk2(wa.z, wa.w);
            unsigned long long wb01 = pk2(wb.x, wb.y), wb23 = pk2(wb.z, wb.w);
            #pragma unroll
            for (int rr = 0; rr < R; rr++) {
                float4 x = sx[(rg * R + rr) * I2 + i2];
                unsigned long long x01 = pk2(x.x, x.y), x23 = pk2(x.z, x.w);
                ffma2(acca[rr], x01, wa01);
                ffma2(acca[rr], x23, wa23);
                ffma2(accb[rr], x01, wb01);
                ffma2(accb[rr], x23, wb23);
            }
        }

        #pragma unroll
        for (int rr = 0; rr < R; rr++) {
            float sga, bia_, sgb, bib;
            upk2(acca[rr], sga, bia_);
            upk2(accb[rr], sgb, bib);
            sga  = sga  > 0.f ? sga  : LEAKY * sga;
            bia_ = bia_ > 0.f ? bia_ : LEAKY * bia_;
            sgb  = sgb  > 0.f ? sgb  : LEAKY * sgb;
            bib  = bib  > 0.f ? bib  : LEAKY * bib;
            float outa = sga + bia_;
            float outb = sgb + bib;

            float p = outa * outa + outb * outb;
            #pragma unroll
            for (int o = JW / 2; o > 0; o >>= 1)
                p += __shfl_xor_sync(0xffffffffu, p, o);
            float inv = 1.f / fmaxf(sqrtf(p), 1e-12f);

            int row = base + rg * R + rr;
            if (row < N_NODES) {
                if (WEGO) {
                    ego_out[(size_t)row * DOUT + j]      = outa;
                    ego_out[(size_t)row * DOUT + j + JW] = outb;
                }
                if (W16) {
                    e16[(size_t)row * DOUT + j]      = __float2half(outa);
                    e16[(size_t)row * DOUT + j + JW] = __float2half(outb);
                }
                all_emb[(size_t)row * OUT_COLS + col_off + j]      = outa * inv;
                all_emb[(size_t)row * OUT_COLS + col_off + j + JW] = outb * inv;
            }
        }
        __syncthreads();   // protect sx reuse
    }
}

// ---------------- final gather: (u_e, pos_i_e, neg_i_e) ----------------------
__global__ void gather_kernel(const int* __restrict__ users,
                              const int* __restrict__ pos,
                              const int* __restrict__ neg,
                              const float4* __restrict__ u4,
                              const float4* __restrict__ e4,
                              float4* __restrict__ out4) {
    int gid = blockIdx.x * blockDim.x + threadIdx.x;
    if (gid >= 3 * BATCH * 44) return;
    int idx   = gid / 44;
    int c     = gid - idx * 44;
    int which = idx / BATCH;
    int b     = idx - which * BATCH;
    int row = (which == 0) ? users[b]
            : (which == 1) ? (N_USERS + pos[b])
                           : (N_USERS + neg[b]);
    float4 v;
    if (c < 16) {
        v = (row < N_USERS) ? u4[(size_t)row * 16 + c]
                            : e4[(size_t)(row - N_USERS) * 16 + c];
    } else {
        v = g_all4[(size_t)row * 44 + c];
    }
    out4[gid] = v;
}

// -----------------------------------------------------------------------------
extern "C" void kernel_launch(void* const* d_in, const int* in_sizes, int n_in,
                              void* d_out, int out_size) {
    const int*   users = (const int*)  d_in[0];
    const int*   pos   = (const int*)  d_in[1];
    const int*   neg   = (const int*)  d_in[2];
    const int*   all_h = (const int*)  d_in[3];
    const int*   all_t = (const int*)  d_in[4];
    const float* Aval  = (const float*)d_in[5];
    const float* u_emb = (const float*)d_in[6];
    const float* e_emb = (const float*)d_in[7];
    const float* Wg0 = (const float*)d_in[8];
    const float* bg0 = (const float*)d_in[9];
    const float* Wb0 = (const float*)d_in[10];
    const float* bb0 = (const float*)d_in[11];
    const float* Wg1 = (const float*)d_in[12];
    const float* bg1 = (const float*)d_in[13];
    const float* Wb1 = (const float*)d_in[14];
    const float* bb1 = (const float*)d_in[15];
    const float* Wg2 = (const float*)d_in[16];
    const float* bg2 = (const float*)d_in[17];
    const float* Wb2 = (const float*)d_in[18];
    const float* bb2 = (const float*)d_in[19];

    void *pA, *pB, *pX;
    cudaGetSymbolAddress(&pA, g_egoA4);
    cudaGetSymbolAddress(&pB, g_egoB4);
    cudaGetSymbolAddress(&pX, g_x4);
    void* pAll; cudaGetSymbolAddress(&pAll, g_all4);
    float*  egoA = (float*)pA;
    float*  egoB = (float*)pB;
    float4* x4   = (float4*)pX;
    float*  all  = (float*)pAll;

    const int TB = 256;
    const int GEMM_GRID  = 148 * 8;
    const int AGG64_GRID = (N_NODES * 16 + TB - 1) / TB;
    const int AGG32_GRID = (N_NODES * 8  + TB - 1) / TB;

    // dynamic smem sizes (float4 units -> bytes)
    const int smem0 = (2 * 32 * 33 + 64 * 32 + 32) * 16;   // 64->64, R=8
    const int smem1 = (2 * 16 * 33 + 64 * 32 + 16) * 16;   // 64->32, R=4
    const int smem2 = (2 * 8  * 17 + 128 * 16 + 8) * 16;   // 32->16, R=4
    cudaFuncSetAttribute(gemm_kernel<64, 64, 8, true,  true>,
                         cudaFuncAttributeMaxDynamicSharedMemorySize, smem0);
    cudaFuncSetAttribute(gemm_kernel<64, 32, 4, true,  true>,
                         cudaFuncAttributeMaxDynamicSharedMemorySize, smem1);
    cudaFuncSetAttribute(gemm_kernel<32, 16, 4, false, false>,
                         cudaFuncAttributeMaxDynamicSharedMemorySize, smem2);

    // launch 1: conv0 (also zeroes cursor + scan chain)
    conv0_kernel<<<(N_NODES * 32 + TB - 1) / TB, TB>>>(
        (const float2*)u_emb, (const float2*)e_emb);
    // launch 2-4: CSR build
    hist_kernel<<<(N_EDGES + TB - 1) / TB, TB>>>(all_h);
    scan_kernel<<<SCAN_BLOCKS, 256>>>();
    fill_kernel<<<(N_EDGES + TB - 1) / TB, TB>>>(all_h, all_t, Aval);

    // launch 5: agg64 layer 0  <-- ncu -s 5 profiles THIS now
    agg64_kernel<true><<<AGG64_GRID, TB>>>(
        (const float4*)u_emb, (const float4*)e_emb, x4);
    gemm_kernel<64, 64, 8, true, true><<<GEMM_GRID, TB, smem0>>>(
        x4, egoB, Wg0, bg0, Wb0, bb0, all, 64);

    agg64_kernel<false><<<AGG64_GRID, TB>>>(
        (const float4*)egoB, nullptr, x4);
    gemm_kernel<64, 32, 4, true, true><<<GEMM_GRID, TB, smem1>>>(
        x4, egoA, Wg1, bg1, Wb1, bb1, all, 128);

    agg32_kernel<<<AGG32_GRID, TB>>>((const float4*)egoA, x4);
    gemm_kernel<32, 16, 4, false, false><<<GEMM_GRID, TB, smem2>>>(
        x4, egoB, Wg2, bg2, Wb2, bb2, all, 160);

    gather_kernel<<<(3 * BATCH * 44 + TB - 1) / TB, TB>>>(
        users, pos, neg, (const float4*)u_emb, (const float4*)e_emb,
        (float4*)d_out);
}

// round 16
// speedup vs baseline: 1.1144x; 1.1144x over previous
#include <cuda_runtime.h>
#include <cuda_bf16.h>
#include <cuda_fp16.h>
#include <math.h>

#define N_USERS   50000
#define N_ENT     100000
#define N_NODES   150000
#define N_EDGES   3000000
#define BATCH     8192
#define OUT_COLS  176
#define LEAKY     0.2f

// ---------------- scratch (device globals) -----------------------------------
__device__ float4 g_egoA4[N_NODES * 16];        // layer outputs (<=64 floats/row)
__device__ float4 g_egoB4[N_NODES * 16];
__device__ float4 g_x4  [N_NODES * 32];         // packed {xs,xb} pairs (max 64in)
__device__ float4 g_all4[N_NODES * 44];         // cols [64,176) used
__device__ __half2 g_ego16[N_NODES * 32];       // fp16 gather shadow
__device__ __align__(16) long long g_pairs[N_EDGES];  // {a:hi32, t:lo32} grouped by h
__device__ int g_rowptr[N_NODES + 1];
__device__ int g_cursor[N_NODES];
__device__ int g_partial[256];

#define SCAN_BLOCKS 147                          // 147*1024 >= 150000

// ---------------- f32x2 packed helpers ---------------------------------------
__device__ __forceinline__ unsigned long long pk2(float a, float b) {
    unsigned long long r;
    asm("mov.b64 %0, {%1,%2};" : "=l"(r) : "f"(a), "f"(b));
    return r;
}
__device__ __forceinline__ void upk2(unsigned long long v, float& a, float& b) {
    asm("mov.b64 {%0,%1}, %2;" : "=f"(a), "=f"(b) : "l"(v));
}
__device__ __forceinline__ void ffma2(unsigned long long& acc,
                                      unsigned long long a,
                                      unsigned long long b) {
    asm("fma.rn.f32x2 %0, %1, %2, %0;" : "+l"(acc) : "l"(a), "l"(b));
}
__device__ __forceinline__ longlong2 ldg_ll2(const long long* p) {
    return __ldg(reinterpret_cast<const longlong2*>(p));
}
// load 4 halves (dims 4l..4l+3) -> float4
__device__ __forceinline__ float4 ldg_h4(const __half2* p) {
    uint2 raw = __ldg(reinterpret_cast<const uint2*>(p));
    __half2 h0 = *reinterpret_cast<__half2*>(&raw.x);
    __half2 h1 = *reinterpret_cast<__half2*>(&raw.y);
    float2 f0 = __half22float2(h0);
    float2 f1 = __half22float2(h1);
    return make_float4(f0.x, f0.y, f1.x, f1.y);
}

// ---------------- conv0: fp16 shadow of layer-0 ego + cursor reset ------------
__global__ void conv0_kernel(const float2* __restrict__ u2,
                             const float2* __restrict__ e2) {
    int gid = blockIdx.x * blockDim.x + threadIdx.x;
    if (gid < N_NODES) g_cursor[gid] = 0;            // replaces memsetAsync
    if (gid >= N_NODES * 32) return;
    float2 v = (gid < N_USERS * 32) ? u2[gid] : e2[gid - N_USERS * 32];
    g_ego16[gid] = __float22half2_rn(v);
}

// ================= CSR build (proven 3-pass scan) =============================
__global__ void hist_kernel(const int* __restrict__ all_h) {
    int e = blockIdx.x * blockDim.x + threadIdx.x;
    if (e < N_EDGES) atomicAdd(&g_cursor[all_h[e]], 1);
}

__global__ void scan_pass1() {
    __shared__ int sm[256];
    int tid = threadIdx.x;
    int base = blockIdx.x * 1024 + tid * 4;
    int s = 0;
    #pragma unroll
    for (int k = 0; k < 4; k++) {
        int idx = base + k;
        if (idx < N_NODES) s += g_cursor[idx];
    }
    sm[tid] = s; __syncthreads();
    for (int o = 128; o > 0; o >>= 1) {
        if (tid < o) sm[tid] += sm[tid + o];
        __syncthreads();
    }
    if (tid == 0) g_partial[blockIdx.x] = sm[0];
}

__global__ void scan_pass2() {
    __shared__ int sm[256];
    int tid = threadIdx.x;
    int v = (tid < SCAN_BLOCKS) ? g_partial[tid] : 0;
    sm[tid] = v; __syncthreads();
    for (int o = 1; o < 256; o <<= 1) {
        int t = (tid >= o) ? sm[tid - o] : 0;
        __syncthreads();
        sm[tid] += t;
        __syncthreads();
    }
    if (tid < SCAN_BLOCKS) g_partial[tid] = sm[tid] - v;   // exclusive
    if (tid == 0) g_rowptr[N_NODES] = N_EDGES;
}

__global__ void scan_pass3() {
    __shared__ int sm[256];
    int tid = threadIdx.x;
    int base = blockIdx.x * 1024 + tid * 4;
    int d[4]; int s = 0;
    #pragma unroll
    for (int k = 0; k < 4; k++) {
        int idx = base + k;
        d[k] = (idx < N_NODES) ? g_cursor[idx] : 0;
        s += d[k];
    }
    sm[tid] = s; __syncthreads();
    for (int o = 1; o < 256; o <<= 1) {
        int t = (tid >= o) ? sm[tid - o] : 0;
        __syncthreads();
        sm[tid] += t;
        __syncthreads();
    }
    int run = g_partial[blockIdx.x] + sm[tid] - s;
    #pragma unroll
    for (int k = 0; k < 4; k++) {
        int idx = base + k;
        if (idx < N_NODES) {
            g_rowptr[idx] = run;
            g_cursor[idx] = run;
            run += d[k];
        }
    }
}

__global__ void fill_kernel(const int* __restrict__ all_h,
                            const int* __restrict__ all_t,
                            const float* __restrict__ A) {
    int e = blockIdx.x * blockDim.x + threadIdx.x;
    if (e >= N_EDGES) return;
    int h = all_h[e];
    int p = atomicAdd(&g_cursor[h], 1);
    unsigned long long q = (unsigned long long)(unsigned)all_t[e]
                         | ((unsigned long long)__float_as_uint(A[e]) << 32);
    g_pairs[p] = (long long)q;
}

// ================= aggregation ================================================
__device__ __forceinline__ void unpack_pair(long long q, int& t, float& a) {
    t = (int)(unsigned)q;
    a = __uint_as_float((unsigned)((unsigned long long)q >> 32));
}

// DIN=64: 16 lanes/node, lane l owns dims [4l,4l+4). Gathers from fp16 shadow
// (LDG.64); self term fp32. Pairs read as longlong2.
template <bool SPLIT>
__global__ void agg64_kernel(const float4* __restrict__ egoU,
                             const float4* __restrict__ egoE,
                             float4* __restrict__ x4) {
    int ghw = (blockIdx.x * blockDim.x + threadIdx.x) >> 4;   // node id
    int l   = threadIdx.x & 15;
    if (ghw >= N_NODES) return;
    int s   = __ldg(g_rowptr + ghw);
    int end = __ldg(g_rowptr + ghw + 1);
    float ax = 0.f, ay = 0.f, az = 0.f, aw = 0.f;
    int e = s;
    if (e < end && (e & 1)) {
        int t; float a;
        unpack_pair(__ldg(g_pairs + e), t, a);
        float4 v = ldg_h4(g_ego16 + (size_t)t * 32 + 2 * l);
        ax += a * v.x; ay += a * v.y; az += a * v.z; aw += a * v.w;
        e++;
    }
    for (; e + 4 <= end; e += 4) {
        longlong2 q01 = ldg_ll2(g_pairs + e);
        longlong2 q23 = ldg_ll2(g_pairs + e + 2);
        int t0, t1, t2, t3; float a0, a1, a2, a3;
        unpack_pair(q01.x, t0, a0); unpack_pair(q01.y, t1, a1);
        unpack_pair(q23.x, t2, a2); unpack_pair(q23.y, t3, a3);
        float4 v0 = ldg_h4(g_ego16 + (size_t)t0 * 32 + 2 * l);
        float4 v1 = ldg_h4(g_ego16 + (size_t)t1 * 32 + 2 * l);
        float4 v2 = ldg_h4(g_ego16 + (size_t)t2 * 32 + 2 * l);
        float4 v3 = ldg_h4(g_ego16 + (size_t)t3 * 32 + 2 * l);
        ax += a0 * v0.x; ay += a0 * v0.y; az += a0 * v0.z; aw += a0 * v0.w;
        ax += a1 * v1.x; ay += a1 * v1.y; az += a1 * v1.z; aw += a1 * v1.w;
        ax += a2 * v2.x; ay += a2 * v2.y; az += a2 * v2.z; aw += a2 * v2.w;
        ax += a3 * v3.x; ay += a3 * v3.y; az += a3 * v3.z; aw += a3 * v3.w;
    }
    for (; e < end; e++) {
        int t; float a;
        unpack_pair(__ldg(g_pairs + e), t, a);
        float4 v = ldg_h4(g_ego16 + (size_t)t * 32 + 2 * l);
        ax += a * v.x; ay += a * v.y; az += a * v.z; aw += a * v.w;
    }
    const float4* ps = (!SPLIT || ghw < N_USERS) ? (egoU + (size_t)ghw * 16)
                                                 : (egoE + (size_t)(ghw - N_USERS) * 16);
    float4 eg = __ldg(ps + l);
    x4[(size_t)ghw * 32 + 2 * l]     = make_float4(eg.x + ax, eg.x * ax, eg.y + ay, eg.y * ay);
    x4[(size_t)ghw * 32 + 2 * l + 1] = make_float4(eg.z + az, eg.z * az, eg.w + aw, eg.w * aw);
}

// DIN=32: 8 lanes/node, lane l owns dims [4l,4l+4). fp16 gathers, fp32 self.
__global__ void agg32_kernel(const float4* __restrict__ ego4,
                             float4* __restrict__ x4out) {
    int ghw = (blockIdx.x * blockDim.x + threadIdx.x) >> 3;
    int l   = threadIdx.x & 7;
    if (ghw >= N_NODES) return;
    int s   = __ldg(g_rowptr + ghw);
    int end = __ldg(g_rowptr + ghw + 1);
    float ax = 0.f, ay = 0.f, az = 0.f, aw = 0.f;
    int e = s;
    if (e < end && (e & 1)) {
        int t; float a;
        unpack_pair(__ldg(g_pairs + e), t, a);
        float4 v = ldg_h4(g_ego16 + (size_t)t * 16 + 2 * l);
        ax += a * v.x; ay += a * v.y; az += a * v.z; aw += a * v.w;
        e++;
    }
    for (; e + 4 <= end; e += 4) {
        longlong2 q01 = ldg_ll2(g_pairs + e);
        longlong2 q23 = ldg_ll2(g_pairs + e + 2);
        int t0, t1, t2, t3; float a0, a1, a2, a3;
        unpack_pair(q01.x, t0, a0); unpack_pair(q01.y, t1, a1);
        unpack_pair(q23.x, t2, a2); unpack_pair(q23.y, t3, a3);
        float4 v0 = ldg_h4(g_ego16 + (size_t)t0 * 16 + 2 * l);
        float4 v1 = ldg_h4(g_ego16 + (size_t)t1 * 16 + 2 * l);
        float4 v2 = ldg_h4(g_ego16 + (size_t)t2 * 16 + 2 * l);
        float4 v3 = ldg_h4(g_ego16 + (size_t)t3 * 16 + 2 * l);
        ax += a0 * v0.x; ay += a0 * v0.y; az += a0 * v0.z; aw += a0 * v0.w;
        ax += a1 * v1.x; ay += a1 * v1.y; az += a1 * v1.z; aw += a1 * v1.w;
        ax += a2 * v2.x; ay += a2 * v2.y; az += a2 * v2.z; aw += a2 * v2.w;
        ax += a3 * v3.x; ay += a3 * v3.y; az += a3 * v3.z; aw += a3 * v3.w;
    }
    for (; e < end; e++) {
        int t; float a;
        unpack_pair(__ldg(g_pairs + e), t, a);
        float4 v = ldg_h4(g_ego16 + (size_t)t * 16 + 2 * l);
        ax += a * v.x; ay += a * v.y; az += a * v.z; aw += a * v.w;
    }
    float4 eg = __ldg(ego4 + (size_t)ghw * 8 + l);
    x4out[(size_t)ghw * 16 + 2 * l]     = make_float4(eg.x + ax, eg.x * ax, eg.y + ay, eg.y * ay);
    x4out[(size_t)ghw * 16 + 2 * l + 1] = make_float4(eg.z + az, eg.z * az, eg.w + aw, eg.w * aw);
}

// ================= GEMM + leaky + norm (2-col threads, packed f32x2) ==========
// WEGO: write fp32 ego_out; W16: write fp16 shadow for next layer's gathers.
template <int DIN, int DOUT, int R, bool WEGO, bool W16>
__global__ void __launch_bounds__(256)
gemm_kernel(const float4* __restrict__ x4,
            float* __restrict__ ego_out,
            const float* __restrict__ Wg,
            const float* __restrict__ bg,
            const float* __restrict__ Wb,
            const float* __restrict__ bb,
            float* __restrict__ all_emb,
            int col_off) {
    constexpr int I2   = DIN / 2;
    constexpr int JW   = DOUT / 2;      // threads per row-group
    constexpr int JG   = 256 / JW;      // row-groups per block
    constexpr int ROWS = JG * R;

    extern __shared__ float4 dyn4[];
    float4* sWa   = dyn4;                       // [JW][I2+1]
    float4* sWb   = sWa + JW * (I2 + 1);        // [JW][I2+1]
    float4* sx    = sWb + JW * (I2 + 1);        // [ROWS][I2]
    float4* sbias = sx + ROWS * I2;             // [JW]

    int tid = threadIdx.x;
    for (int k = tid; k < JW * I2; k += 256) {
        int j  = k % JW;
        int i2 = k / JW;
        sWa[j * (I2 + 1) + i2] = make_float4(Wg[(2 * i2)     * DOUT + j],
                                             Wb[(2 * i2)     * DOUT + j],
                                             Wg[(2 * i2 + 1) * DOUT + j],
                                             Wb[(2 * i2 + 1) * DOUT + j]);
        int j2 = j + JW;
        sWb[j * (I2 + 1) + i2] = make_float4(Wg[(2 * i2)     * DOUT + j2],
                                             Wb[(2 * i2)     * DOUT + j2],
                                             Wg[(2 * i2 + 1) * DOUT + j2],
                                             Wb[(2 * i2 + 1) * DOUT + j2]);
    }
    if (tid < JW) sbias[tid] = make_float4(bg[tid], bb[tid], bg[tid + JW], bb[tid + JW]);
    __syncthreads();

    int rg = tid / JW;
    int j  = tid % JW;
    float4 bia = sbias[j];
    __half* e16 = reinterpret_cast<__half*>(g_ego16);

    for (int base = blockIdx.x * ROWS; base < N_NODES; base += gridDim.x * ROWS) {
        {
            const float4* src = x4 + (size_t)base * I2;
            int limit = (N_NODES - base) * I2;
            int total = ROWS * I2;
            for (int k = tid; k < total; k += 256)
                if (k < limit) sx[k] = src[k];
        }
        __syncthreads();

        unsigned long long acca[R], accb[R];
        #pragma unroll
        for (int rr = 0; rr < R; rr++) {
            acca[rr] = pk2(bia.x, bia.y);
            accb[rr] = pk2(bia.z, bia.w);
        }

        #pragma unroll
        for (int i2 = 0; i2 < I2; i2++) {
            float4 wa = sWa[j * (I2 + 1) + i2];
            float4 wb = sWb[j * (I2 + 1) + i2];
            unsigned long long wa01 = pk2(wa.x, wa.y), wa23 = pk2(wa.z, wa.w);
            unsigned long long wb01 = pk2(wb.x, wb.y), wb23 = pk2(wb.z, wb.w);
            #pragma unroll
            for (int rr = 0; rr < R; rr++) {
                float4 x = sx[(rg * R + rr) * I2 + i2];
                unsigned long long x01 = pk2(x.x, x.y), x23 = pk2(x.z, x.w);
                ffma2(acca[rr], x01, wa01);
                ffma2(acca[rr], x23, wa23);
                ffma2(accb[rr], x01, wb01);
                ffma2(accb[rr], x23, wb23);
            }
        }

        #pragma unroll
        for (int rr = 0; rr < R; rr++) {
            float sga, bia_, sgb, bib;
            upk2(acca[rr], sga, bia_);
            upk2(accb[rr], sgb, bib);
            sga  = sga  > 0.f ? sga  : LEAKY * sga;
            bia_ = bia_ > 0.f ? bia_ : LEAKY * bia_;
            sgb  = sgb  > 0.f ? sgb  : LEAKY * sgb;
            bib  = bib  > 0.f ? bib  : LEAKY * bib;
            float outa = sga + bia_;
            float outb = sgb + bib;

            float p = outa * outa + outb * outb;
            #pragma unroll
            for (int o = JW / 2; o > 0; o >>= 1)
                p += __shfl_xor_sync(0xffffffffu, p, o);
            float inv = 1.f / fmaxf(sqrtf(p), 1e-12f);

            int row = base + rg * R + rr;
            if (row < N_NODES) {
                if (WEGO) {
                    ego_out[(size_t)row * DOUT + j]      = outa;
                    ego_out[(size_t)row * DOUT + j + JW] = outb;
                }
                if (W16) {
                    e16[(size_t)row * DOUT + j]      = __float2half(outa);
                    e16[(size_t)row * DOUT + j + JW] = __float2half(outb);
                }
                all_emb[(size_t)row * OUT_COLS + col_off + j]      = outa * inv;
                all_emb[(size_t)row * OUT_COLS + col_off + j + JW] = outb * inv;
            }
        }
        __syncthreads();   // protect sx reuse
    }
}

// ---------------- final gather: (u_e, pos_i_e, neg_i_e) ----------------------
__global__ void gather_kernel(const int* __restrict__ users,
                              const int* __restrict__ pos,
                              const int* __restrict__ neg,
                              const float4* __restrict__ u4,
                              const float4* __restrict__ e4,
                              float4* __restrict__ out4) {
    int gid = blockIdx.x * blockDim.x + threadIdx.x;
    if (gid >= 3 * BATCH * 44) return;
    int idx   = gid / 44;
    int c     = gid - idx * 44;
    int which = idx / BATCH;
    int b     = idx - which * BATCH;
    int row = (which == 0) ? users[b]
            : (which == 1) ? (N_USERS + pos[b])
                           : (N_USERS + neg[b]);
    float4 v;
    if (c < 16) {
        v = (row < N_USERS) ? u4[(size_t)row * 16 + c]
                            : e4[(size_t)(row - N_USERS) * 16 + c];
    } else {
        v = g_all4[(size_t)row * 44 + c];
    }
    out4[gid] = v;
}

// -----------------------------------------------------------------------------
extern "C" void kernel_launch(void* const* d_in, const int* in_sizes, int n_in,
                              void* d_out, int out_size) {
    const int*   users = (const int*)  d_in[0];
    const int*   pos   = (const int*)  d_in[1];
    const int*   neg   = (const int*)  d_in[2];
    const int*   all_h = (const int*)  d_in[3];
    const int*   all_t = (const int*)  d_in[4];
    const float* Aval  = (const float*)d_in[5];
    const float* u_emb = (const float*)d_in[6];
    const float* e_emb = (const float*)d_in[7];
    const float* Wg0 = (const float*)d_in[8];
    const float* bg0 = (const float*)d_in[9];
    const float* Wb0 = (const float*)d_in[10];
    const float* bb0 = (const float*)d_in[11];
    const float* Wg1 = (const float*)d_in[12];
    const float* bg1 = (const float*)d_in[13];
    const float* Wb1 = (const float*)d_in[14];
    const float* bb1 = (const float*)d_in[15];
    const float* Wg2 = (const float*)d_in[16];
    const float* bg2 = (const float*)d_in[17];
    const float* Wb2 = (const float*)d_in[18];
    const float* bb2 = (const float*)d_in[19];

    void *pA, *pB, *pX;
    cudaGetSymbolAddress(&pA, g_egoA4);
    cudaGetSymbolAddress(&pB, g_egoB4);
    cudaGetSymbolAddress(&pX, g_x4);
    void* pAll; cudaGetSymbolAddress(&pAll, g_all4);
    float*  egoA = (float*)pA;
    float*  egoB = (float*)pB;
    float4* x4   = (float4*)pX;
    float*  all  = (float*)pAll;

    const int TB = 256;
    const int GEMM_GRID  = 148 * 8;
    const int AGG64_GRID = (N_NODES * 16 + TB - 1) / TB;
    const int AGG32_GRID = (N_NODES * 8  + TB - 1) / TB;

    // dynamic smem sizes (float4 units -> bytes)
    const int smem0 = (2 * 32 * 33 + 64 * 32 + 32) * 16;   // 64->64, R=8
    const int smem1 = (2 * 16 * 33 + 64 * 32 + 16) * 16;   // 64->32, R=4
    const int smem2 = (2 * 8  * 17 + 128 * 16 + 8) * 16;   // 32->16, R=4
    cudaFuncSetAttribute(gemm_kernel<64, 64, 8, true,  true>,
                         cudaFuncAttributeMaxDynamicSharedMemorySize, smem0);
    cudaFuncSetAttribute(gemm_kernel<64, 32, 4, true,  true>,
                         cudaFuncAttributeMaxDynamicSharedMemorySize, smem1);
    cudaFuncSetAttribute(gemm_kernel<32, 16, 4, false, false>,
                         cudaFuncAttributeMaxDynamicSharedMemorySize, smem2);

    // conv0 (also zeroes cursor)
    conv0_kernel<<<(N_NODES * 32 + TB - 1) / TB, TB>>>(
        (const float2*)u_emb, (const float2*)e_emb);
    // CSR build (3-pass scan: log-depth, no serial chain)
    hist_kernel<<<(N_EDGES + TB - 1) / TB, TB>>>(all_h);
    scan_pass1<<<SCAN_BLOCKS, 256>>>();
    scan_pass2<<<1, 256>>>();
    scan_pass3<<<SCAN_BLOCKS, 256>>>();
    fill_kernel<<<(N_EDGES + TB - 1) / TB, TB>>>(all_h, all_t, Aval);

    // ---- layer 0: 64 -> 64 (embeds -> egoB), norm to cols [64,128) ----
    agg64_kernel<true><<<AGG64_GRID, TB>>>(
        (const float4*)u_emb, (const float4*)e_emb, x4);
    gemm_kernel<64, 64, 8, true, true><<<GEMM_GRID, TB, smem0>>>(
        x4, egoB, Wg0, bg0, Wb0, bb0, all, 64);

    // ---- layer 1: 64 -> 32 (egoB -> egoA), norm to cols [128,160) ----
    agg64_kernel<false><<<AGG64_GRID, TB>>>(
        (const float4*)egoB, nullptr, x4);
    gemm_kernel<64, 32, 4, true, true><<<GEMM_GRID, TB, smem1>>>(
        x4, egoA, Wg1, bg1, Wb1, bb1, all, 128);

    // ---- layer 2: 32 -> 16 (egoA -> egoB), norm to cols [160,176) ----
    agg32_kernel<<<AGG32_GRID, TB>>>((const float4*)egoA, x4);
    gemm_kernel<32, 16, 4, false, false><<<GEMM_GRID, TB, smem2>>>(
        x4, egoB, Wg2, bg2, Wb2, bb2, all, 160);

    // ---- batched gather ----
    gather_kernel<<<(3 * BATCH * 44 + TB - 1) / TB, TB>>>(
        users, pos, neg, (const float4*)u_emb, (const float4*)e_emb,
        (float4*)d_out);
}

// round 17
// speedup vs baseline: 1.1256x; 1.0100x over previous
#include <cuda_runtime.h>
#include <cuda_bf16.h>
#include <cuda_fp16.h>
#include <math.h>

#define N_USERS   50000
#define N_ENT     100000
#define N_NODES   150000
#define N_EDGES   3000000
#define BATCH     8192
#define OUT_COLS  176
#define LEAKY     0.2f

// ---------------- scratch (device globals) -----------------------------------
__device__ float4 g_egoA4[N_NODES * 16];        // layer outputs (<=64 floats/row)
__device__ float4 g_egoB4[N_NODES * 16];
__device__ float4 g_x4  [N_NODES * 32];         // packed {xs,xb} pairs (max 64in)
__device__ float4 g_all4[N_NODES * 44];         // cols [64,176) used
__device__ __half2 g_ego16[N_NODES * 32];       // fp16 gather shadow
__device__ __align__(16) long long g_pairs[N_EDGES];  // {a:hi32, t:lo32} grouped by h
__device__ int g_rank[N_EDGES];                 // edge rank within its head node
__device__ int g_rowptr[N_NODES + 1];
__device__ int g_cursor[N_NODES];
__device__ int g_partial[256];

#define SCAN_BLOCKS 147                          // 147*1024 >= 150000

// ---------------- f32x2 packed helpers ---------------------------------------
__device__ __forceinline__ unsigned long long pk2(float a, float b) {
    unsigned long long r;
    asm("mov.b64 %0, {%1,%2};" : "=l"(r) : "f"(a), "f"(b));
    return r;
}
__device__ __forceinline__ void upk2(unsigned long long v, float& a, float& b) {
    asm("mov.b64 {%0,%1}, %2;" : "=f"(a), "=f"(b) : "l"(v));
}
__device__ __forceinline__ void ffma2(unsigned long long& acc,
                                      unsigned long long a,
                                      unsigned long long b) {
    asm("fma.rn.f32x2 %0, %1, %2, %0;" : "+l"(acc) : "l"(a), "l"(b));
}
__device__ __forceinline__ longlong2 ldg_ll2(const long long* p) {
    return __ldg(reinterpret_cast<const longlong2*>(p));
}
// load 4 halves (dims 4l..4l+3) -> float4
__device__ __forceinline__ float4 ldg_h4(const __half2* p) {
    uint2 raw = __ldg(reinterpret_cast<const uint2*>(p));
    __half2 h0 = *reinterpret_cast<__half2*>(&raw.x);
    __half2 h1 = *reinterpret_cast<__half2*>(&raw.y);
    float2 f0 = __half22float2(h0);
    float2 f1 = __half22float2(h1);
    return make_float4(f0.x, f0.y, f1.x, f1.y);
}

// ---------------- conv0: fp16 shadow of layer-0 ego + cursor reset ------------
__global__ void conv0_kernel(const float2* __restrict__ u2,
                             const float2* __restrict__ e2) {
    int gid = blockIdx.x * blockDim.x + threadIdx.x;
    if (gid < N_NODES) g_cursor[gid] = 0;            // replaces memsetAsync
    if (gid >= N_NODES * 32) return;
    float2 v = (gid < N_USERS * 32) ? u2[gid] : e2[gid - N_USERS * 32];
    g_ego16[gid] = __float22half2_rn(v);
}

// ================= CSR build ==================================================
// ONE returning-atomic pass: rank[e] = old count. Final cursor = degrees.
__global__ void histrank_kernel(const int* __restrict__ all_h) {
    int e = blockIdx.x * blockDim.x + threadIdx.x;
    if (e < N_EDGES) g_rank[e] = atomicAdd(&g_cursor[all_h[e]], 1);
}

__global__ void scan_pass1() {
    __shared__ int sm[256];
    int tid = threadIdx.x;
    int base = blockIdx.x * 1024 + tid * 4;
    int s = 0;
    #pragma unroll
    for (int k = 0; k < 4; k++) {
        int idx = base + k;
        if (idx < N_NODES) s += g_cursor[idx];
    }
    sm[tid] = s; __syncthreads();
    for (int o = 128; o > 0; o >>= 1) {
        if (tid < o) sm[tid] += sm[tid + o];
        __syncthreads();
    }
    if (tid == 0) g_partial[blockIdx.x] = sm[0];
}

// fused pass2+3: every block re-scans the 147 partials (cheap, removes a launch)
__global__ void scan_pass23() {
    __shared__ int sp[256];
    __shared__ int sm[256];
    int tid = threadIdx.x;
    int bid = blockIdx.x;

    int v = (tid < SCAN_BLOCKS) ? g_partial[tid] : 0;
    sp[tid] = v; __syncthreads();
    for (int o = 1; o < 256; o <<= 1) {               // inclusive scan of partials
        int t = (tid >= o) ? sp[tid - o] : 0;
        __syncthreads();
        sp[tid] += t;
        __syncthreads();
    }
    int block_prefix = (bid > 0) ? sp[bid - 1] : 0;   // exclusive prefix for this block

    int base = bid * 1024 + tid * 4;
    int d[4]; int s = 0;
    #pragma unroll
    for (int k = 0; k < 4; k++) {
        int idx = base + k;
        d[k] = (idx < N_NODES) ? g_cursor[idx] : 0;
        s += d[k];
    }
    sm[tid] = s; __syncthreads();
    for (int o = 1; o < 256; o <<= 1) {
        int t = (tid >= o) ? sm[tid - o] : 0;
        __syncthreads();
        sm[tid] += t;
        __syncthreads();
    }
    int run = block_prefix + sm[tid] - s;
    #pragma unroll
    for (int k = 0; k < 4; k++) {
        int idx = base + k;
        if (idx < N_NODES) {
            g_rowptr[idx] = run;
            run += d[k];
        }
    }
    if (bid == 0 && tid == 0) g_rowptr[N_NODES] = N_EDGES;
}

// pure streaming fill: slot = rowptr[h] + rank[e]; no atomics.
__global__ void fill_kernel(const int* __restrict__ all_h,
                            const int* __restrict__ all_t,
                            const float* __restrict__ A) {
    int e = blockIdx.x * blockDim.x + threadIdx.x;
    if (e >= N_EDGES) return;
    int h = all_h[e];
    int p = __ldg(g_rowptr + h) + g_rank[e];
    unsigned long long q = (unsigned long long)(unsigned)all_t[e]
                         | ((unsigned long long)__float_as_uint(A[e]) << 32);
    g_pairs[p] = (long long)q;
}

// ================= aggregation ================================================
__device__ __forceinline__ void unpack_pair(long long q, int& t, float& a) {
    t = (int)(unsigned)q;
    a = __uint_as_float((unsigned)((unsigned long long)q >> 32));
}

// DIN=64: 16 lanes/node, lane l owns dims [4l,4l+4). Gathers from fp16 shadow
// (LDG.64); self term fp32. Pairs read as longlong2.
template <bool SPLIT>
__global__ void agg64_kernel(const float4* __restrict__ egoU,
                             const float4* __restrict__ egoE,
                             float4* __restrict__ x4) {
    int ghw = (blockIdx.x * blockDim.x + threadIdx.x) >> 4;   // node id
    int l   = threadIdx.x & 15;
    if (ghw >= N_NODES) return;
    int s   = __ldg(g_rowptr + ghw);
    int end = __ldg(g_rowptr + ghw + 1);
    float ax = 0.f, ay = 0.f, az = 0.f, aw = 0.f;
    int e = s;
    if (e < end && (e & 1)) {
        int t; float a;
        unpack_pair(__ldg(g_pairs + e), t, a);
        float4 v = ldg_h4(g_ego16 + (size_t)t * 32 + 2 * l);
        ax += a * v.x; ay += a * v.y; az += a * v.z; aw += a * v.w;
        e++;
    }
    for (; e + 4 <= end; e += 4) {
        longlong2 q01 = ldg_ll2(g_pairs + e);
        longlong2 q23 = ldg_ll2(g_pairs + e + 2);
        int t0, t1, t2, t3; float a0, a1, a2, a3;
        unpack_pair(q01.x, t0, a0); unpack_pair(q01.y, t1, a1);
        unpack_pair(q23.x, t2, a2); unpack_pair(q23.y, t3, a3);
        float4 v0 = ldg_h4(g_ego16 + (size_t)t0 * 32 + 2 * l);
        float4 v1 = ldg_h4(g_ego16 + (size_t)t1 * 32 + 2 * l);
        float4 v2 = ldg_h4(g_ego16 + (size_t)t2 * 32 + 2 * l);
        float4 v3 = ldg_h4(g_ego16 + (size_t)t3 * 32 + 2 * l);
        ax += a0 * v0.x; ay += a0 * v0.y; az += a0 * v0.z; aw += a0 * v0.w;
        ax += a1 * v1.x; ay += a1 * v1.y; az += a1 * v1.z; aw += a1 * v1.w;
        ax += a2 * v2.x; ay += a2 * v2.y; az += a2 * v2.z; aw += a2 * v2.w;
        ax += a3 * v3.x; ay += a3 * v3.y; az += a3 * v3.z; aw += a3 * v3.w;
    }
    for (; e < end; e++) {
        int t; float a;
        unpack_pair(__ldg(g_pairs + e), t, a);
        float4 v = ldg_h4(g_ego16 + (size_t)t * 32 + 2 * l);
        ax += a * v.x; ay += a * v.y; az += a * v.z; aw += a * v.w;
    }
    const float4* ps = (!SPLIT || ghw < N_USERS) ? (egoU + (size_t)ghw * 16)
                                                 : (egoE + (size_t)(ghw - N_USERS) * 16);
    float4 eg = __ldg(ps + l);
    x4[(size_t)ghw * 32 + 2 * l]     = make_float4(eg.x + ax, eg.x * ax, eg.y + ay, eg.y * ay);
    x4[(size_t)ghw * 32 + 2 * l + 1] = make_float4(eg.z + az, eg.z * az, eg.w + aw, eg.w * aw);
}

// DIN=32: 8 lanes/node, lane l owns dims [4l,4l+4). fp16 gathers, fp32 self.
__global__ void agg32_kernel(const float4* __restrict__ ego4,
                             float4* __restrict__ x4out) {
    int ghw = (blockIdx.x * blockDim.x + threadIdx.x) >> 3;
    int l   = threadIdx.x & 7;
    if (ghw >= N_NODES) return;
    int s   = __ldg(g_rowptr + ghw);
    int end = __ldg(g_rowptr + ghw + 1);
    float ax = 0.f, ay = 0.f, az = 0.f, aw = 0.f;
    int e = s;
    if (e < end && (e & 1)) {
        int t; float a;
        unpack_pair(__ldg(g_pairs + e), t, a);
        float4 v = ldg_h4(g_ego16 + (size_t)t * 16 + 2 * l);
        ax += a * v.x; ay += a * v.y; az += a * v.z; aw += a * v.w;
        e++;
    }
    for (; e + 4 <= end; e += 4) {
        longlong2 q01 = ldg_ll2(g_pairs + e);
        longlong2 q23 = ldg_ll2(g_pairs + e + 2);
        int t0, t1, t2, t3; float a0, a1, a2, a3;
        unpack_pair(q01.x, t0, a0); unpack_pair(q01.y, t1, a1);
        unpack_pair(q23.x, t2, a2); unpack_pair(q23.y, t3, a3);
        float4 v0 = ldg_h4(g_ego16 + (size_t)t0 * 16 + 2 * l);
        float4 v1 = ldg_h4(g_ego16 + (size_t)t1 * 16 + 2 * l);
        float4 v2 = ldg_h4(g_ego16 + (size_t)t2 * 16 + 2 * l);
        float4 v3 = ldg_h4(g_ego16 + (size_t)t3 * 16 + 2 * l);
        ax += a0 * v0.x; ay += a0 * v0.y; az += a0 * v0.z; aw += a0 * v0.w;
        ax += a1 * v1.x; ay += a1 * v1.y; az += a1 * v1.z; aw += a1 * v1.w;
        ax += a2 * v2.x; ay += a2 * v2.y; az += a2 * v2.z; aw += a2 * v2.w;
        ax += a3 * v3.x; ay += a3 * v3.y; az += a3 * v3.z; aw += a3 * v3.w;
    }
    for (; e < end; e++) {
        int t; float a;
        unpack_pair(__ldg(g_pairs + e), t, a);
        float4 v = ldg_h4(g_ego16 + (size_t)t * 16 + 2 * l);
        ax += a * v.x; ay += a * v.y; az += a * v.z; aw += a * v.w;
    }
    float4 eg = __ldg(ego4 + (size_t)ghw * 8 + l);
    x4out[(size_t)ghw * 16 + 2 * l]     = make_float4(eg.x + ax, eg.x * ax, eg.y + ay, eg.y * ay);
    x4out[(size_t)ghw * 16 + 2 * l + 1] = make_float4(eg.z + az, eg.z * az, eg.w + aw, eg.w * aw);
}

// ================= GEMM + leaky + norm (2-col threads, packed f32x2) ==========
// WEGO: write fp32 ego_out; W16: write fp16 shadow for next layer's gathers.
template <int DIN, int DOUT, int R, bool WEGO, bool W16>
__global__ void __launch_bounds__(256)
gemm_kernel(const float4* __restrict__ x4,
            float* __restrict__ ego_out,
            const float* __restrict__ Wg,
            const float* __restrict__ bg,
            const float* __restrict__ Wb,
            const float* __restrict__ bb,
            float* __restrict__ all_emb,
            int col_off) {
    constexpr int I2   = DIN / 2;
    constexpr int JW   = DOUT / 2;      // threads per row-group
    constexpr int JG   = 256 / JW;      // row-groups per block
    constexpr int ROWS = JG * R;

    extern __shared__ float4 dyn4[];
    float4* sWa   = dyn4;                       // [JW][I2+1]
    float4* sWb   = sWa + JW * (I2 + 1);        // [JW][I2+1]
    float4* sx    = sWb + JW * (I2 + 1);        // [ROWS][I2]
    float4* sbias = sx + ROWS * I2;             // [JW]

    int tid = threadIdx.x;
    for (int k = tid; k < JW * I2; k += 256) {
        int j  = k % JW;
        int i2 = k / JW;
        sWa[j * (I2 + 1) + i2] = make_float4(Wg[(2 * i2)     * DOUT + j],
                                             Wb[(2 * i2)     * DOUT + j],
                                             Wg[(2 * i2 + 1) * DOUT + j],
                                             Wb[(2 * i2 + 1) * DOUT + j]);
        int j2 = j + JW;
        sWb[j * (I2 + 1) + i2] = make_float4(Wg[(2 * i2)     * DOUT + j2],
                                             Wb[(2 * i2)     * DOUT + j2],
                                             Wg[(2 * i2 + 1) * DOUT + j2],
                                             Wb[(2 * i2 + 1) * DOUT + j2]);
    }
    if (tid < JW) sbias[tid] = make_float4(bg[tid], bb[tid], bg[tid + JW], bb[tid + JW]);
    __syncthreads();

    int rg = tid / JW;
    int j  = tid % JW;
    float4 bia = sbias[j];
    __half* e16 = reinterpret_cast<__half*>(g_ego16);

    for (int base = blockIdx.x * ROWS; base < N_NODES; base += gridDim.x * ROWS) {
        {
            const float4* src = x4 + (size_t)base * I2;
            int limit = (N_NODES - base) * I2;
            int total = ROWS * I2;
            for (int k = tid; k < total; k += 256)
                if (k < limit) sx[k] = src[k];
        }
        __syncthreads();

        unsigned long long acca[R], accb[R];
        #pragma unroll
        for (int rr = 0; rr < R; rr++) {
            acca[rr] = pk2(bia.x, bia.y);
            accb[rr] = pk2(bia.z, bia.w);
        }

        #pragma unroll
        for (int i2 = 0; i2 < I2; i2++) {
            float4 wa = sWa[j * (I2 + 1) + i2];
            float4 wb = sWb[j * (I2 + 1) + i2];
            unsigned long long wa01 = pk2(wa.x, wa.y), wa23 = pk2(wa.z, wa.w);
            unsigned long long wb01 = pk2(wb.x, wb.y), wb23 = pk2(wb.z, wb.w);
            #pragma unroll
            for (int rr = 0; rr < R; rr++) {
                float4 x = sx[(rg * R + rr) * I2 + i2];
                unsigned long long x01 = pk2(x.x, x.y), x23 = pk2(x.z, x.w);
                ffma2(acca[rr], x01, wa01);
                ffma2(acca[rr], x23, wa23);
                ffma2(accb[rr], x01, wb01);
                ffma2(accb[rr], x23, wb23);
            }
        }

        #pragma unroll
        for (int rr = 0; rr < R; rr++) {
            float sga, bia_, sgb, bib;
            upk2(acca[rr], sga, bia_);
            upk2(accb[rr], sgb, bib);
            sga  = sga  > 0.f ? sga  : LEAKY * sga;
            bia_ = bia_ > 0.f ? bia_ : LEAKY * bia_;
            sgb  = sgb  > 0.f ? sgb  : LEAKY * sgb;
            bib  = bib  > 0.f ? bib  : LEAKY * bib;
            float outa = sga + bia_;
            float outb = sgb + bib;

            float p = outa * outa + outb * outb;
            #pragma unroll
            for (int o = JW / 2; o > 0; o >>= 1)
                p += __shfl_xor_sync(0xffffffffu, p, o);
            float inv = 1.f / fmaxf(sqrtf(p), 1e-12f);

            int row = base + rg * R + rr;
            if (row < N_NODES) {
                if (WEGO) {
                    ego_out[(size_t)row * DOUT + j]      = outa;
                    ego_out[(size_t)row * DOUT + j + JW] = outb;
                }
                if (W16) {
                    e16[(size_t)row * DOUT + j]      = __float2half(outa);
                    e16[(size_t)row * DOUT + j + JW] = __float2half(outb);
                }
                all_emb[(size_t)row * OUT_COLS + col_off + j]      = outa * inv;
                all_emb[(size_t)row * OUT_COLS + col_off + j + JW] = outb * inv;
            }
        }
        __syncthreads();   // protect sx reuse
    }
}

// ---------------- final gather: (u_e, pos_i_e, neg_i_e) ----------------------
__global__ void gather_kernel(const int* __restrict__ users,
                              const int* __restrict__ pos,
                              const int* __restrict__ neg,
                              const float4* __restrict__ u4,
                              const float4* __restrict__ e4,
                              float4* __restrict__ out4) {
    int gid = blockIdx.x * blockDim.x + threadIdx.x;
    if (gid >= 3 * BATCH * 44) return;
    int idx   = gid / 44;
    int c     = gid - idx * 44;
    int which = idx / BATCH;
    int b     = idx - which * BATCH;
    int row = (which == 0) ? users[b]
            : (which == 1) ? (N_USERS + pos[b])
                           : (N_USERS + neg[b]);
    float4 v;
    if (c < 16) {
        v = (row < N_USERS) ? u4[(size_t)row * 16 + c]
                            : e4[(size_t)(row - N_USERS) * 16 + c];
    } else {
        v = g_all4[(size_t)row * 44 + c];
    }
    out4[gid] = v;
}

// -----------------------------------------------------------------------------
extern "C" void kernel_launch(void* const* d_in, const int* in_sizes, int n_in,
                              void* d_out, int out_size) {
    const int*   users = (const int*)  d_in[0];
    const int*   pos   = (const int*)  d_in[1];
    const int*   neg   = (const int*)  d_in[2];
    const int*   all_h = (const int*)  d_in[3];
    const int*   all_t = (const int*)  d_in[4];
    const float* Aval  = (const float*)d_in[5];
    const float* u_emb = (const float*)d_in[6];
    const float* e_emb = (const float*)d_in[7];
    const float* Wg0 = (const float*)d_in[8];
    const float* bg0 = (const float*)d_in[9];
    const float* Wb0 = (const float*)d_in[10];
    const float* bb0 = (const float*)d_in[11];
    const float* Wg1 = (const float*)d_in[12];
    const float* bg1 = (const float*)d_in[13];
    const float* Wb1 = (const float*)d_in[14];
    const float* bb1 = (const float*)d_in[15];
    const float* Wg2 = (const float*)d_in[16];
    const float* bg2 = (const float*)d_in[17];
    const float* Wb2 = (const float*)d_in[18];
    const float* bb2 = (const float*)d_in[19];

    void *pA, *pB, *pX;
    cudaGetSymbolAddress(&pA, g_egoA4);
    cudaGetSymbolAddress(&pB, g_egoB4);
    cudaGetSymbolAddress(&pX, g_x4);
    void* pAll; cudaGetSymbolAddress(&pAll, g_all4);
    float*  egoA = (float*)pA;
    float*  egoB = (float*)pB;
    float4* x4   = (float4*)pX;
    float*  all  = (float*)pAll;

    const int TB = 256;
    const int GEMM_GRID  = 148 * 8;
    const int AGG64_GRID = (N_NODES * 16 + TB - 1) / TB;
    const int AGG32_GRID = (N_NODES * 8  + TB - 1) / TB;

    // dynamic smem sizes (float4 units -> bytes)
    const int smem0 = (2 * 32 * 33 + 64 * 32 + 32) * 16;   // 64->64, R=8
    const int smem1 = (2 * 16 * 33 + 64 * 32 + 16) * 16;   // 64->32, R=4
    const int smem2 = (2 * 8  * 17 + 128 * 16 + 8) * 16;   // 32->16, R=4
    cudaFuncSetAttribute(gemm_kernel<64, 64, 8, true,  true>,
                         cudaFuncAttributeMaxDynamicSharedMemorySize, smem0);
    cudaFuncSetAttribute(gemm_kernel<64, 32, 4, true,  true>,
                         cudaFuncAttributeMaxDynamicSharedMemorySize, smem1);
    cudaFuncSetAttribute(gemm_kernel<32, 16, 4, false, false>,
                         cudaFuncAttributeMaxDynamicSharedMemorySize, smem2);

    // conv0 (also zeroes cursor)
    conv0_kernel<<<(N_NODES * 32 + TB - 1) / TB, TB>>>(
        (const float2*)u_emb, (const float2*)e_emb);
    // CSR build: ONE atomic pass (rank), 2-kernel scan, streaming fill
    histrank_kernel<<<(N_EDGES + TB - 1) / TB, TB>>>(all_h);
    scan_pass1<<<SCAN_BLOCKS, 256>>>();
    scan_pass23<<<SCAN_BLOCKS, 256>>>();
    fill_kernel<<<(N_EDGES + TB - 1) / TB, TB>>>(all_h, all_t, Aval);

    // ---- layer 0: 64 -> 64 (embeds -> egoB), norm to cols [64,128) ----
    agg64_kernel<true><<<AGG64_GRID, TB>>>(
        (const float4*)u_emb, (const float4*)e_emb, x4);
    gemm_kernel<64, 64, 8, true, true><<<GEMM_GRID, TB, smem0>>>(
        x4, egoB, Wg0, bg0, Wb0, bb0, all, 64);

    // ---- layer 1: 64 -> 32 (egoB -> egoA), norm to cols [128,160) ----
    agg64_kernel<false><<<AGG64_GRID, TB>>>(
        (const float4*)egoB, nullptr, x4);
    gemm_kernel<64, 32, 4, true, true><<<GEMM_GRID, TB, smem1>>>(
        x4, egoA, Wg1, bg1, Wb1, bb1, all, 128);

    // ---- layer 2: 32 -> 16 (egoA -> egoB), norm to cols [160,176) ----
    agg32_kernel<<<AGG32_GRID, TB>>>((const float4*)egoA, x4);
    gemm_kernel<32, 16, 4, false, false><<<GEMM_GRID, TB, smem2>>>(
        x4, egoB, Wg2, bg2, Wb2, bb2, all, 160);

    // ---- batched gather ----
    gather_kernel<<<(3 * BATCH * 44 + TB - 1) / TB, TB>>>(
        users, pos, neg, (const float4*)u_emb, (const float4*)e_emb,
        (float4*)d_out);
}